// round 13
// baseline (speedup 1.0000x reference)
#include <cuda_runtime.h>
#include <cuda_fp16.h>
#include <cstdint>

#define NN 50000
#define NE 800000
#define NG 512
#define NB 196            // ceil(NN/256)

// ---------------- scratch ----------------
__device__ float g_agg[(size_t)NN * 128];    // holds MEAN after gather
__device__ float g_h1[(size_t)NN * 128];
__device__ uint32_t g_x16[(size_t)NN * 64];  // fp16x2 copy of x   (gather source)
__device__ uint32_t g_h116[(size_t)NN * 64]; // fp16x2 copy of h1  (gather source)
__device__ float g_pool[NG * 128];
__device__ int g_src[NE];
__device__ int g_dst[NE];
__device__ int g_ssrc[NE];                  // src ids grouped by dst (CSR)
__device__ int g_deg[NN];
__device__ int g_off[NN + 1];
__device__ int g_cur[NN];
__device__ int g_bsum[256];
__device__ int g_bat[NN];
__device__ int g_eflag = 0;   // 1 => edge_index stored as int32 (input-determined, sticky)
__device__ int g_bflag = 0;
__device__ int g_cnt0;
__device__ int g_cnt1;
__device__ int g_cnt2;

// ---------------- helpers ----------------
__device__ __forceinline__ uint32_t smem_u32(const void* p) {
    return (uint32_t)__cvta_generic_to_shared(p);
}

__device__ __forceinline__ uint32_t packf16(float a, float b) {
    __half2 h = __floats2half2_rn(a, b);
    return *(uint32_t*)&h;
}

// fp16 hi/lo split: A-side error ~2^-22, dominated by B's single-fp16 2^-12.
__device__ __forceinline__ void splitf16(float a, float b, uint32_t& hi, uint32_t& lo) {
    __half ah = __float2half_rn(a);
    __half bh = __float2half_rn(b);
    __half al = __float2half_rn(a - __half2float(ah));
    __half bl = __float2half_rn(b - __half2float(bh));
    hi = (uint32_t)__half_as_ushort(ah) | ((uint32_t)__half_as_ushort(bh) << 16);
    lo = (uint32_t)__half_as_ushort(al) | ((uint32_t)__half_as_ushort(bl) << 16);
}

__device__ __forceinline__ void mma16816(float* c, const uint32_t* a,
                                         uint32_t b0, uint32_t b1) {
    asm volatile(
        "mma.sync.aligned.m16n8k16.row.col.f32.f16.f16.f32 "
        "{%0,%1,%2,%3}, {%4,%5,%6,%7}, {%8,%9}, {%0,%1,%2,%3};"
        : "+f"(c[0]), "+f"(c[1]), "+f"(c[2]), "+f"(c[3])
        : "r"(a[0]), "r"(a[1]), "r"(a[2]), "r"(a[3]), "r"(b0), "r"(b1));
}

__device__ __forceinline__ void ldsm4(uint32_t* r, uint32_t addr) {
    asm volatile("ldmatrix.sync.aligned.m8n8.x4.shared.b16 {%0,%1,%2,%3}, [%4];"
                 : "=r"(r[0]), "=r"(r[1]), "=r"(r[2]), "=r"(r[3]) : "r"(addr));
}

__device__ __forceinline__ void h8acc(uint4 raw, float* f) {
    float2 a = __half22float2(*(__half2*)&raw.x);
    float2 b = __half22float2(*(__half2*)&raw.y);
    float2 c = __half22float2(*(__half2*)&raw.z);
    float2 d = __half22float2(*(__half2*)&raw.w);
    f[0] += a.x; f[1] += a.y; f[2] += b.x; f[3] += b.y;
    f[4] += c.x; f[5] += c.y; f[6] += d.x; f[7] += d.y;
}

// ---------------- init: zero + dtype detect ----------------
// Sample 64-bit words: true int64 indices are < 50000, so any word >= 2^32
// means the buffer actually holds packed int32 values. Flags are sticky and
// input-determined, so they are never reset (static init zeroes them once).
__global__ void init_kernel(const unsigned long long* __restrict__ e_raw,
                            const unsigned long long* __restrict__ b_raw) {
    int i = blockIdx.x * blockDim.x + threadIdx.x;
    int stride = gridDim.x * blockDim.x;
    if (i == 0) { g_cnt0 = 0; g_cnt1 = 0; g_cnt2 = 0; }
    for (int j = i; j < NN; j += stride) g_deg[j] = 0;
    for (int j = i; j < NG * 128; j += stride) g_pool[j] = 0.f;
    if (i < 4096) {
        if (e_raw[i] >= (1ull << 32)) atomicExch(&g_eflag, 1);
        if (i < 2048 && b_raw[i] >= (1ull << 32)) atomicExch(&g_bflag, 1);
    }
}

// ---------------- prep: convert + x->fp16 + scan + scatter ----------------
__device__ __forceinline__ void grid_sync(int* cnt, int t) {
    __threadfence();
    __syncthreads();
    if (t == 0) {
        atomicAdd(cnt, 1);
        while (*(volatile int*)cnt < NB) { __nanosleep(64); }
    }
    __syncthreads();
}

__global__ void __launch_bounds__(256) prep_kernel(const void* __restrict__ e_raw,
                                                   const void* __restrict__ b_raw,
                                                   const float* __restrict__ x) {
    __shared__ int s[256];
    __shared__ int bo[256];
    __shared__ int bs[256];
    int t = threadIdx.x, b = blockIdx.x;
    int i = b * 256 + t;

    // phase 0: normalize indices + degree histogram + x -> fp16
    {
        int eflag = g_eflag, bflag = g_bflag;
        for (int e = i; e < NE; e += NB * 256) {
            int ss, dd;
            if (eflag) {
                ss = ((const int*)e_raw)[e];
                dd = ((const int*)e_raw)[NE + e];
            } else {
                ss = (int)((const long long*)e_raw)[e];
                dd = (int)((const long long*)e_raw)[NE + e];
            }
            g_src[e] = ss;
            g_dst[e] = dd;
            atomicAdd(&g_deg[dd], 1);
        }
        for (int n = i; n < NN; n += NB * 256) {
            g_bat[n] = bflag ? ((const int*)b_raw)[n]
                             : (int)((const long long*)b_raw)[n];
        }
        for (int idx = i; idx < NN * 64; idx += NB * 256) {
            float2 v = ((const float2*)x)[idx];
            g_x16[idx] = packf16(v.x, v.y);
        }
    }
    grid_sync(&g_cnt0, t);

    // phase 1: block-local exclusive scan of degrees
    int d = (i < NN) ? g_deg[i] : 0;
    s[t] = d;
    __syncthreads();
    #pragma unroll
    for (int off = 1; off < 256; off <<= 1) {
        int v = (t >= off) ? s[t - off] : 0;
        __syncthreads();
        s[t] += v;
        __syncthreads();
    }
    int loc = s[t] - d;
    if (t == 255) g_bsum[b] = s[255];
    grid_sync(&g_cnt1, t);

    // phase 2: every block scans the block sums (redundant, cheap)
    int v = (t < NB) ? g_bsum[t] : 0;
    bo[t] = v; bs[t] = v;
    __syncthreads();
    #pragma unroll
    for (int off = 1; off < 256; off <<= 1) {
        int u = (t >= off) ? bs[t - off] : 0;
        __syncthreads();
        bs[t] += u;
        __syncthreads();
    }
    int base = bs[b] - bo[b];
    if (i < NN) { int o = loc + base; g_off[i] = o; g_cur[i] = o; }
    if (i == 0) g_off[NN] = NE;
    grid_sync(&g_cnt2, t);

    // phase 3: scatter src ids into CSR order
    for (int e = i; e < NE; e += NB * 256) {
        int dd = g_dst[e];
        int pos = atomicAdd(&g_cur[dd], 1);
        g_ssrc[pos] = g_src[e];
    }
}

// ---------------- CSR gather (fp16 rows): warp per node, half-warp per edge --
// 16 lanes x uint4 cover one 256B fp16 row; a warp runs two edge streams.
__global__ void gather_kernel(const uint32_t* __restrict__ feat16,
                              float* __restrict__ aggout) {
    int lane = threadIdx.x & 31;
    int node = (int)((blockIdx.x * (long long)blockDim.x + threadIdx.x) >> 5);
    if (node >= NN) return;
    int half = lane >> 4, hl = lane & 15;
    int beg = g_off[node], end = g_off[node + 1];
    float f[8] = {0.f, 0.f, 0.f, 0.f, 0.f, 0.f, 0.f, 0.f};
    int e = beg + half;
    // unroll 4: this half-stream handles edges e, e+2, e+4, e+6
    for (; e + 6 < end; e += 8) {
        uint4 v[4];
        #pragma unroll
        for (int j = 0; j < 4; j++) {
            int sj = g_ssrc[e + 2 * j];
            v[j] = ((const uint4*)feat16)[(long long)sj * 16 + hl];
        }
        #pragma unroll
        for (int j = 0; j < 4; j++) h8acc(v[j], f);
    }
    for (; e < end; e += 2) {
        int sj = g_ssrc[e];
        h8acc(((const uint4*)feat16)[(long long)sj * 16 + hl], f);
    }
    // combine the two half-warp streams
    #pragma unroll
    for (int j = 0; j < 8; j++)
        f[j] += __shfl_xor_sync(0xffffffffu, f[j], 16);
    float inv = 1.f / (float)max(end - beg, 1);
    if (half == 0) {
        float4* dst = (float4*)(aggout + (long long)node * 128);
        dst[hl * 2] = make_float4(f[0] * inv, f[1] * inv, f[2] * inv, f[3] * inv);
        dst[hl * 2 + 1] = make_float4(f[4] * inv, f[5] * inv, f[6] * inv, f[7] * inv);
    }
}

// ---------------- smem layout (bytes) — 64-row tiles, 2 CTAs/SM ----------------
#define SM_BIAS 0
#define SM_AHI  512
#define SM_ALO  17920
#define SM_EPI  512
#define SM_BH   35328
#define SM_TOTAL 102912
#define ASTR 272     // A row stride bytes (136 f16)
#define BSTR 528     // B row stride bytes (264 f16)

// ---------------- SAGE conv via mma.sync fp16x2, 512 thr, 2 CTAs/SM ----------
// 16 warps, warp tile = 16 rows x 32 cols over a 64x128 output tile.
// A split fp16 hi/lo, B single fp16; staging prefetched during MMA phases.
// out[i][c] = bl[c] + mean[i]@Wl[c] + xin[i]@Wr[c]   (K = 256 = [mean|x])
__global__ void __launch_bounds__(512, 2) conv_mma_kernel(
    const float* __restrict__ meanm, const float* __restrict__ xin,
    const float* __restrict__ Wl, const float* __restrict__ bl,
    const float* __restrict__ Wr, float* __restrict__ outp,
    uint32_t* __restrict__ out16, int to_pool) {
    extern __shared__ char sm[];
    float* sBias = (float*)(sm + SM_BIAS);
    float* sEpi  = (float*)(sm + SM_EPI);
    int tid = threadIdx.x;
    int w = tid >> 5, lane = tid & 31;
    int quad = lane >> 2, tq = lane & 3;
    int rgrp = (w & 3) * 16;          // warp's 16 rows (MMA, 64-row tile)
    int cgrp = (w >> 2) * 32;         // warp's 32 cols (MMA)

    if (tid < 128) sBias[tid] = bl[tid];

    // stage both weight matrices once: B[n][k] single fp16, k = [Wl | Wr]
    for (int idx = tid; idx < 128 * 64; idx += 512) {
        int c = idx >> 6, p = idx & 63;
        float2 wl2 = ((const float2*)Wl)[idx];
        float2 wr2 = ((const float2*)Wr)[idx];
        *(uint32_t*)(sm + SM_BH + c * BSTR + 4 * p) = packf16(wl2.x, wl2.y);
        *(uint32_t*)(sm + SM_BH + c * BSTR + 256 + 4 * p) = packf16(wr2.x, wr2.y);
    }
    __syncthreads();

    const uint32_t smb = smem_u32(sm);
    int arow = (lane & 7) + ((lane >> 3) & 1) * 8;
    uint32_t aoff = (uint32_t)((rgrp + arow) * ASTR + (lane >> 4) * 16);
    uint32_t aHi = smb + SM_AHI + aoff;
    uint32_t aLo = smb + SM_ALO + aoff;
    int brow = (lane & 7) + ((lane >> 4) & 1) * 8;
    uint32_t boff = (uint32_t)((cgrp + brow) * BSTR + ((lane >> 3) & 1) * 16);
    uint32_t bH = smb + SM_BH + boff;

    // staging item coords (4 items: idx = tid + j*512, covers 64 rows x 32 quads)
    int sr[4], sq[4];
    #pragma unroll
    for (int j = 0; j < 4; j++) {
        int idx = tid + j * 512;
        sr[j] = idx >> 5; sq[j] = idx & 31;
    }

    // prefetch first tile's mean half
    float4 pf[4];
    int tb = blockIdx.x * 64;
    #pragma unroll
    for (int j = 0; j < 4; j++) {
        int grow = tb + sr[j];
        pf[j] = (grow < NN) ? ((const float4*)meanm)[(long long)grow * 32 + sq[j]]
                            : make_float4(0.f, 0.f, 0.f, 0.f);
    }

    for (int tile = blockIdx.x; tile * 64 < NN; tile += gridDim.x) {
        tb = tile * 64;
        float acc[4][4];
        #pragma unroll
        for (int nt = 0; nt < 4; nt++)
            #pragma unroll
            for (int j = 0; j < 4; j++) acc[nt][j] = 0.f;

        // store prefetched mean half into A smem
        #pragma unroll
        for (int j = 0; j < 4; j++) {
            uint32_t h0, l0, h1, l1;
            splitf16(pf[j].x, pf[j].y, h0, l0);
            splitf16(pf[j].z, pf[j].w, h1, l1);
            *(uint2*)(sm + SM_AHI + sr[j] * ASTR + 8 * sq[j]) = make_uint2(h0, h1);
            *(uint2*)(sm + SM_ALO + sr[j] * ASTR + 8 * sq[j]) = make_uint2(l0, l1);
        }
        __syncthreads();

        // prefetch root half (in flight during MMA h0)
        #pragma unroll
        for (int j = 0; j < 4; j++) {
            int grow = tb + sr[j];
            pf[j] = (grow < NN) ? ((const float4*)xin)[(long long)grow * 32 + sq[j]]
                                : make_float4(0.f, 0.f, 0.f, 0.f);
        }

        // MMA half 0 (mean @ Wl)
        #pragma unroll
        for (int ks = 0; ks < 8; ks++) {
            uint32_t ah[4], al[4];
            ldsm4(ah, aHi + ks * 32);
            ldsm4(al, aLo + ks * 32);
            #pragma unroll
            for (int ntp = 0; ntp < 2; ntp++) {
                uint32_t bh[4];
                ldsm4(bh, bH + (uint32_t)(ntp * 16 * BSTR) + ks * 32);
                int n0 = ntp * 2, n1 = ntp * 2 + 1;
                mma16816(acc[n0], ah, bh[0], bh[1]);
                mma16816(acc[n1], ah, bh[2], bh[3]);
                mma16816(acc[n0], al, bh[0], bh[1]);
                mma16816(acc[n1], al, bh[2], bh[3]);
            }
        }
        __syncthreads();

        // store root half
        #pragma unroll
        for (int j = 0; j < 4; j++) {
            uint32_t h0, l0, h1, l1;
            splitf16(pf[j].x, pf[j].y, h0, l0);
            splitf16(pf[j].z, pf[j].w, h1, l1);
            *(uint2*)(sm + SM_AHI + sr[j] * ASTR + 8 * sq[j]) = make_uint2(h0, h1);
            *(uint2*)(sm + SM_ALO + sr[j] * ASTR + 8 * sq[j]) = make_uint2(l0, l1);
        }
        __syncthreads();

        // prefetch next tile's mean half (in flight during MMA h1)
        {
            int ntb = tb + gridDim.x * 64;
            #pragma unroll
            for (int j = 0; j < 4; j++) {
                int grow = ntb + sr[j];
                pf[j] = (grow < NN) ? ((const float4*)meanm)[(long long)grow * 32 + sq[j]]
                                    : make_float4(0.f, 0.f, 0.f, 0.f);
            }
        }

        // MMA half 1 (x @ Wr)
        #pragma unroll
        for (int ks = 0; ks < 8; ks++) {
            uint32_t ah[4], al[4];
            ldsm4(ah, aHi + ks * 32);
            ldsm4(al, aLo + ks * 32);
            #pragma unroll
            for (int ntp = 0; ntp < 2; ntp++) {
                uint32_t bh[4];
                ldsm4(bh, bH + (uint32_t)(ntp * 16 * BSTR) + 256u + ks * 32);
                int n0 = ntp * 2, n1 = ntp * 2 + 1;
                mma16816(acc[n0], ah, bh[0], bh[1]);
                mma16816(acc[n1], ah, bh[2], bh[3]);
                mma16816(acc[n0], al, bh[0], bh[1]);
                mma16816(acc[n1], al, bh[2], bh[3]);
            }
        }
        __syncthreads();

        // epilogue: regs -> smem (f32) -> coalesced out / pool
        #pragma unroll
        for (int nt = 0; nt < 4; nt++) {
            int r0 = rgrp + quad;
            int c = cgrp + nt * 8 + tq * 2;
            *(float2*)&sEpi[r0 * 132 + c] = make_float2(acc[nt][0], acc[nt][1]);
            *(float2*)&sEpi[(r0 + 8) * 132 + c] = make_float2(acc[nt][2], acc[nt][3]);
        }
        __syncthreads();
        for (int idx = tid; idx < 64 * 32; idx += 512) {
            int r = idx >> 5, q = idx & 31;
            int grow = tb + r;
            if (grow < NN) {
                float4 v = *(float4*)&sEpi[r * 132 + 4 * q];
                float4 b = *(float4*)&sBias[4 * q];
                v.x += b.x; v.y += b.y; v.z += b.z; v.w += b.w;
                if (to_pool) {
                    float* p = g_pool + (long long)g_bat[grow] * 128 + 4 * q;
                    asm volatile("red.global.add.v4.f32 [%0], {%1,%2,%3,%4};"
                                 :: "l"(p), "f"(v.x), "f"(v.y), "f"(v.z), "f"(v.w)
                                 : "memory");
                } else {
                    ((float4*)outp)[(long long)grow * 32 + q] = v;
                    ((uint2*)out16)[(long long)grow * 32 + q] =
                        make_uint2(packf16(v.x, v.y), packf16(v.z, v.w));
                }
            }
        }
        __syncthreads();
    }
}

// ---------------- head: lin1 + BN(eval) + relu + lin2 ----------------
__global__ void __launch_bounds__(128) head_kernel(
    const float* __restrict__ lin1w, const float* __restrict__ lin1b,
    const float* __restrict__ lin2w, const float* __restrict__ lin2b,
    const float* __restrict__ gamma, const float* __restrict__ beta,
    const float* __restrict__ rmean, const float* __restrict__ rvar,
    float* __restrict__ out) {
    int g = blockIdx.x;
    int c = threadIdx.x;
    __shared__ float p[128];
    __shared__ float h[128];
    p[c] = g_pool[g * 128 + c];
    __syncthreads();
    float acc = lin1b[c];
    const float* w = lin1w + c * 128;
    #pragma unroll 8
    for (int k = 0; k < 128; k++) acc += p[k] * w[k];
    acc = (acc - rmean[c]) * rsqrtf(rvar[c] + 1e-5f) * gamma[c] + beta[c];
    h[c] = fmaxf(acc, 0.f);
    __syncthreads();
    int wid = c >> 5, lane = c & 31;
    if (wid < 2) {
        const float* w2 = lin2w + wid * 128;
        float s = 0.f;
        #pragma unroll
        for (int k = lane; k < 128; k += 32) s += h[k] * w2[k];
        #pragma unroll
        for (int o = 16; o; o >>= 1) s += __shfl_xor_sync(0xffffffffu, s, o);
        if (lane == 0) out[g * 2 + wid] = s + lin2b[wid];
    }
}

// ---------------- launch ----------------
extern "C" void kernel_launch(void* const* d_in, const int* in_sizes, int n_in,
                              void* d_out, int out_size) {
    const float* x        = (const float*)d_in[0];
    const void*  ei_raw   = (const void*)d_in[1];
    const void*  bat_raw  = (const void*)d_in[2];
    const float* W1l      = (const float*)d_in[3];
    const float* b1       = (const float*)d_in[4];
    const float* W1r      = (const float*)d_in[5];
    const float* W2l      = (const float*)d_in[6];
    const float* b2       = (const float*)d_in[7];
    const float* W2r      = (const float*)d_in[8];
    const float* lin1w    = (const float*)d_in[9];
    const float* lin1b    = (const float*)d_in[10];
    const float* lin2w    = (const float*)d_in[11];
    const float* lin2b    = (const float*)d_in[12];
    const float* gamma    = (const float*)d_in[13];
    const float* beta     = (const float*)d_in[14];
    const float* rmean    = (const float*)d_in[15];
    const float* rvar     = (const float*)d_in[16];
    float* out            = (float*)d_out;

    float *agg, *h1;
    uint32_t *x16, *h116;
    cudaGetSymbolAddress((void**)&agg, g_agg);
    cudaGetSymbolAddress((void**)&h1, g_h1);
    cudaGetSymbolAddress((void**)&x16, g_x16);
    cudaGetSymbolAddress((void**)&h116, g_h116);

    cudaFuncSetAttribute(conv_mma_kernel,
                         cudaFuncAttributeMaxDynamicSharedMemorySize, SM_TOTAL);

    const int gat_grid = (NN * 32 + 255) / 256;    // warp per node

    init_kernel<<<256, 256>>>((const unsigned long long*)ei_raw,
                              (const unsigned long long*)bat_raw);
    prep_kernel<<<NB, 256>>>(ei_raw, bat_raw, x);
    gather_kernel<<<gat_grid, 256>>>(x16, agg);
    conv_mma_kernel<<<296, 512, SM_TOTAL>>>(agg, x, W1l, b1, W1r, h1, h116, 0);
    gather_kernel<<<gat_grid, 256>>>(h116, agg);
    conv_mma_kernel<<<296, 512, SM_TOTAL>>>(agg, h1, W2l, b2, W2r, nullptr,
                                            nullptr, 1);
    head_kernel<<<NG, 128>>>(lin1w, lin1b, lin2w, lin2b,
                             gamma, beta, rmean, rvar, out);
}

// round 14
// speedup vs baseline: 1.0153x; 1.0153x over previous
#include <cuda_runtime.h>
#include <cuda_fp16.h>
#include <cstdint>

#define NN 50000
#define NE 800000
#define NG 512
#define NB 196            // ceil(NN/256)

// ---------------- scratch ----------------
__device__ float g_agg[(size_t)NN * 128];    // holds MEAN after gather
__device__ float g_h1[(size_t)NN * 128];
__device__ uint32_t g_x16[(size_t)NN * 64];  // fp16x2 copy of x   (gather source)
__device__ uint32_t g_h116[(size_t)NN * 64]; // fp16x2 copy of h1  (gather source)
__device__ float g_pool[NG * 128];
__device__ int g_src[NE];
__device__ int g_dst[NE];
__device__ int g_ssrc[NE];                  // src ids grouped by dst (CSR)
__device__ int g_deg[NN];
__device__ int g_off[NN + 1];
__device__ int g_cur[NN];
__device__ int g_bsum[256];
__device__ int g_bat[NN];
__device__ int g_eflag = 0;   // 1 => edge_index stored as int32 (input-determined, sticky)
__device__ int g_bflag = 0;
__device__ int g_cnt0;
__device__ int g_cnt1;
__device__ int g_cnt2;

// ---------------- helpers ----------------
__device__ __forceinline__ uint32_t smem_u32(const void* p) {
    return (uint32_t)__cvta_generic_to_shared(p);
}

__device__ __forceinline__ uint32_t packf16(float a, float b) {
    __half2 h = __floats2half2_rn(a, b);
    return *(uint32_t*)&h;
}

// fp16 hi/lo split: A-side error ~2^-22, dominated by B's single-fp16 2^-12.
__device__ __forceinline__ void splitf16(float a, float b, uint32_t& hi, uint32_t& lo) {
    __half ah = __float2half_rn(a);
    __half bh = __float2half_rn(b);
    __half al = __float2half_rn(a - __half2float(ah));
    __half bl = __float2half_rn(b - __half2float(bh));
    hi = (uint32_t)__half_as_ushort(ah) | ((uint32_t)__half_as_ushort(bh) << 16);
    lo = (uint32_t)__half_as_ushort(al) | ((uint32_t)__half_as_ushort(bl) << 16);
}

__device__ __forceinline__ void mma16816(float* c, const uint32_t* a,
                                         uint32_t b0, uint32_t b1) {
    asm volatile(
        "mma.sync.aligned.m16n8k16.row.col.f32.f16.f16.f32 "
        "{%0,%1,%2,%3}, {%4,%5,%6,%7}, {%8,%9}, {%0,%1,%2,%3};"
        : "+f"(c[0]), "+f"(c[1]), "+f"(c[2]), "+f"(c[3])
        : "r"(a[0]), "r"(a[1]), "r"(a[2]), "r"(a[3]), "r"(b0), "r"(b1));
}

__device__ __forceinline__ void ldsm4(uint32_t* r, uint32_t addr) {
    asm volatile("ldmatrix.sync.aligned.m8n8.x4.shared.b16 {%0,%1,%2,%3}, [%4];"
                 : "=r"(r[0]), "=r"(r[1]), "=r"(r[2]), "=r"(r[3]) : "r"(addr));
}

__device__ __forceinline__ void h4acc(uint2 raw, float4& acc) {
    __half2 h0 = *(__half2*)&raw.x;
    __half2 h1 = *(__half2*)&raw.y;
    float2 f0 = __half22float2(h0);
    float2 f1 = __half22float2(h1);
    acc.x += f0.x; acc.y += f0.y; acc.z += f1.x; acc.w += f1.y;
}

// ---------------- init: zero + dtype detect ----------------
// Sample 64-bit words: true int64 indices are < 50000, so any word >= 2^32
// means the buffer actually holds packed int32 values. Flags are sticky and
// input-determined, so they are never reset (static init zeroes them once).
__global__ void init_kernel(const unsigned long long* __restrict__ e_raw,
                            const unsigned long long* __restrict__ b_raw) {
    int i = blockIdx.x * blockDim.x + threadIdx.x;
    int stride = gridDim.x * blockDim.x;
    if (i == 0) { g_cnt0 = 0; g_cnt1 = 0; g_cnt2 = 0; }
    for (int j = i; j < NN; j += stride) g_deg[j] = 0;
    for (int j = i; j < NG * 128; j += stride) g_pool[j] = 0.f;
    if (i < 4096) {
        if (e_raw[i] >= (1ull << 32)) atomicExch(&g_eflag, 1);
        if (i < 2048 && b_raw[i] >= (1ull << 32)) atomicExch(&g_bflag, 1);
    }
}

// ---------------- prep: convert + x->fp16 + scan + scatter ----------------
__device__ __forceinline__ void grid_sync(int* cnt, int t) {
    __threadfence();
    __syncthreads();
    if (t == 0) {
        atomicAdd(cnt, 1);
        while (*(volatile int*)cnt < NB) { __nanosleep(64); }
    }
    __syncthreads();
}

__global__ void __launch_bounds__(256) prep_kernel(const void* __restrict__ e_raw,
                                                   const void* __restrict__ b_raw,
                                                   const float* __restrict__ x) {
    __shared__ int s[256];
    __shared__ int bo[256];
    __shared__ int bs[256];
    int t = threadIdx.x, b = blockIdx.x;
    int i = b * 256 + t;

    // phase 0: normalize indices + degree histogram + x -> fp16
    {
        int eflag = g_eflag, bflag = g_bflag;
        for (int e = i; e < NE; e += NB * 256) {
            int ss, dd;
            if (eflag) {
                ss = ((const int*)e_raw)[e];
                dd = ((const int*)e_raw)[NE + e];
            } else {
                ss = (int)((const long long*)e_raw)[e];
                dd = (int)((const long long*)e_raw)[NE + e];
            }
            g_src[e] = ss;
            g_dst[e] = dd;
            atomicAdd(&g_deg[dd], 1);
        }
        for (int n = i; n < NN; n += NB * 256) {
            g_bat[n] = bflag ? ((const int*)b_raw)[n]
                             : (int)((const long long*)b_raw)[n];
        }
        for (int idx = i; idx < NN * 64; idx += NB * 256) {
            float2 v = ((const float2*)x)[idx];
            g_x16[idx] = packf16(v.x, v.y);
        }
    }
    grid_sync(&g_cnt0, t);

    // phase 1: block-local exclusive scan of degrees
    int d = (i < NN) ? g_deg[i] : 0;
    s[t] = d;
    __syncthreads();
    #pragma unroll
    for (int off = 1; off < 256; off <<= 1) {
        int v = (t >= off) ? s[t - off] : 0;
        __syncthreads();
        s[t] += v;
        __syncthreads();
    }
    int loc = s[t] - d;
    if (t == 255) g_bsum[b] = s[255];
    grid_sync(&g_cnt1, t);

    // phase 2: every block scans the block sums (redundant, cheap)
    int v = (t < NB) ? g_bsum[t] : 0;
    bo[t] = v; bs[t] = v;
    __syncthreads();
    #pragma unroll
    for (int off = 1; off < 256; off <<= 1) {
        int u = (t >= off) ? bs[t - off] : 0;
        __syncthreads();
        bs[t] += u;
        __syncthreads();
    }
    int base = bs[b] - bo[b];
    if (i < NN) { int o = loc + base; g_off[i] = o; g_cur[i] = o; }
    if (i == 0) g_off[NN] = NE;
    grid_sync(&g_cnt2, t);

    // phase 3: scatter src ids into CSR order
    for (int e = i; e < NE; e += NB * 256) {
        int dd = g_dst[e];
        int pos = atomicAdd(&g_cur[dd], 1);
        g_ssrc[pos] = g_src[e];
    }
}

// ---------------- CSR gather (fp16 rows): warp per dst node, writes MEAN ----
__global__ void gather_kernel(const uint32_t* __restrict__ feat16,
                              float* __restrict__ aggout) {
    int lane = threadIdx.x & 31;
    int node = (int)((blockIdx.x * (long long)blockDim.x + threadIdx.x) >> 5);
    if (node >= NN) return;
    int beg = g_off[node], end = g_off[node + 1];
    float4 acc = make_float4(0.f, 0.f, 0.f, 0.f);
    int e = beg;
    for (; e + 7 < end; e += 8) {
        uint2 v[8];
        #pragma unroll
        for (int j = 0; j < 8; j++) {
            int sj = g_ssrc[e + j];
            v[j] = ((const uint2*)feat16)[(long long)sj * 32 + lane];
        }
        #pragma unroll
        for (int j = 0; j < 8; j++) h4acc(v[j], acc);
    }
    for (; e + 3 < end; e += 4) {
        uint2 v[4];
        #pragma unroll
        for (int j = 0; j < 4; j++) {
            int sj = g_ssrc[e + j];
            v[j] = ((const uint2*)feat16)[(long long)sj * 32 + lane];
        }
        #pragma unroll
        for (int j = 0; j < 4; j++) h4acc(v[j], acc);
    }
    for (; e < end; e++) {
        int s0 = g_ssrc[e];
        h4acc(((const uint2*)feat16)[(long long)s0 * 32 + lane], acc);
    }
    float inv = 1.f / (float)max(end - beg, 1);
    acc.x *= inv; acc.y *= inv; acc.z *= inv; acc.w *= inv;
    ((float4*)(aggout + (long long)node * 128))[lane] = acc;
}

// ---------------- smem layout (bytes) ----------------
#define SM_BIAS 0
#define SM_AHI  512
#define SM_ALO  35328
#define SM_EPI  512
#define SM_BH   70144
#define SM_TOTAL 137728
#define ASTR 272     // A row stride bytes (136 f16)
#define BSTR 528     // B row stride bytes (264 f16)

// ---------------- SAGE conv via mma.sync fp16x2, 1024 threads ----------------
// 32 warps, warp tile = 16 rows x 32 cols. A split fp16 hi/lo, B single fp16.
// MMA issue order: all 4 accumulators with ah, then all 4 with al
// (accumulator reuse distance 4 to cover HMMA RAW latency).
// out[i][c] = bl[c] + mean[i]@Wl[c] + xin[i]@Wr[c]   (K = 256 = [mean|x])
__global__ void __launch_bounds__(1024, 1) conv_mma_kernel(
    const float* __restrict__ meanm, const float* __restrict__ xin,
    const float* __restrict__ Wl, const float* __restrict__ bl,
    const float* __restrict__ Wr, float* __restrict__ outp,
    uint32_t* __restrict__ out16, int to_pool) {
    extern __shared__ char sm[];
    float* sBias = (float*)(sm + SM_BIAS);
    float* sEpi  = (float*)(sm + SM_EPI);
    int tid = threadIdx.x;
    int w = tid >> 5, lane = tid & 31;
    int quad = lane >> 2, tq = lane & 3;
    int rgrp = (w & 7) * 16;          // warp's 16 rows (MMA)
    int cgrp = (w >> 3) * 32;         // warp's 32 cols (MMA)

    if (tid < 128) sBias[tid] = bl[tid];

    // stage both weight matrices once: B[n][k] single fp16, k = [Wl | Wr]
    for (int idx = tid; idx < 128 * 64; idx += 1024) {
        int c = idx >> 6, p = idx & 63;
        float2 wl2 = ((const float2*)Wl)[idx];
        float2 wr2 = ((const float2*)Wr)[idx];
        *(uint32_t*)(sm + SM_BH + c * BSTR + 4 * p) = packf16(wl2.x, wl2.y);
        *(uint32_t*)(sm + SM_BH + c * BSTR + 256 + 4 * p) = packf16(wr2.x, wr2.y);
    }
    __syncthreads();

    const uint32_t smb = smem_u32(sm);
    int arow = (lane & 7) + ((lane >> 3) & 1) * 8;
    uint32_t aoff = (uint32_t)((rgrp + arow) * ASTR + (lane >> 4) * 16);
    uint32_t aHi = smb + SM_AHI + aoff;
    uint32_t aLo = smb + SM_ALO + aoff;
    int brow = (lane & 7) + ((lane >> 4) & 1) * 8;
    uint32_t boff = (uint32_t)((cgrp + brow) * BSTR + ((lane >> 3) & 1) * 16);
    uint32_t bH = smb + SM_BH + boff;

    // staging item coords for this thread (4 items: idx = tid + j*1024)
    int sr[4], sq[4];
    #pragma unroll
    for (int j = 0; j < 4; j++) {
        int idx = tid + j * 1024;
        sr[j] = idx >> 5; sq[j] = idx & 31;
    }

    // prefetch first tile's mean half
    float4 pf[4];
    int tb = blockIdx.x * 128;
    #pragma unroll
    for (int j = 0; j < 4; j++) {
        int grow = tb + sr[j];
        pf[j] = (grow < NN) ? ((const float4*)meanm)[(long long)grow * 32 + sq[j]]
                            : make_float4(0.f, 0.f, 0.f, 0.f);
    }

    for (int tile = blockIdx.x; tile * 128 < NN; tile += gridDim.x) {
        tb = tile * 128;
        float acc[4][4];
        #pragma unroll
        for (int nt = 0; nt < 4; nt++)
            #pragma unroll
            for (int j = 0; j < 4; j++) acc[nt][j] = 0.f;

        // store prefetched mean half into A smem
        #pragma unroll
        for (int j = 0; j < 4; j++) {
            uint32_t h0, l0, h1, l1;
            splitf16(pf[j].x, pf[j].y, h0, l0);
            splitf16(pf[j].z, pf[j].w, h1, l1);
            *(uint2*)(sm + SM_AHI + sr[j] * ASTR + 8 * sq[j]) = make_uint2(h0, h1);
            *(uint2*)(sm + SM_ALO + sr[j] * ASTR + 8 * sq[j]) = make_uint2(l0, l1);
        }
        __syncthreads();

        // prefetch root half (in flight during MMA h0)
        #pragma unroll
        for (int j = 0; j < 4; j++) {
            int grow = tb + sr[j];
            pf[j] = (grow < NN) ? ((const float4*)xin)[(long long)grow * 32 + sq[j]]
                                : make_float4(0.f, 0.f, 0.f, 0.f);
        }

        // MMA half 0 (mean @ Wl) — reuse-distance-4 issue order
        #pragma unroll
        for (int ks = 0; ks < 8; ks++) {
            uint32_t ah[4], al[4], bh0[4], bh1[4];
            ldsm4(ah, aHi + ks * 32);
            ldsm4(al, aLo + ks * 32);
            ldsm4(bh0, bH + ks * 32);
            ldsm4(bh1, bH + (uint32_t)(16 * BSTR) + ks * 32);
            mma16816(acc[0], ah, bh0[0], bh0[1]);
            mma16816(acc[1], ah, bh0[2], bh0[3]);
            mma16816(acc[2], ah, bh1[0], bh1[1]);
            mma16816(acc[3], ah, bh1[2], bh1[3]);
            mma16816(acc[0], al, bh0[0], bh0[1]);
            mma16816(acc[1], al, bh0[2], bh0[3]);
            mma16816(acc[2], al, bh1[0], bh1[1]);
            mma16816(acc[3], al, bh1[2], bh1[3]);
        }
        __syncthreads();

        // store root half
        #pragma unroll
        for (int j = 0; j < 4; j++) {
            uint32_t h0, l0, h1, l1;
            splitf16(pf[j].x, pf[j].y, h0, l0);
            splitf16(pf[j].z, pf[j].w, h1, l1);
            *(uint2*)(sm + SM_AHI + sr[j] * ASTR + 8 * sq[j]) = make_uint2(h0, h1);
            *(uint2*)(sm + SM_ALO + sr[j] * ASTR + 8 * sq[j]) = make_uint2(l0, l1);
        }
        __syncthreads();

        // prefetch next tile's mean half (in flight during MMA h1)
        {
            int ntb = tb + gridDim.x * 128;
            #pragma unroll
            for (int j = 0; j < 4; j++) {
                int grow = ntb + sr[j];
                pf[j] = (grow < NN) ? ((const float4*)meanm)[(long long)grow * 32 + sq[j]]
                                    : make_float4(0.f, 0.f, 0.f, 0.f);
            }
        }

        // MMA half 1 (x @ Wr) — reuse-distance-4 issue order
        #pragma unroll
        for (int ks = 0; ks < 8; ks++) {
            uint32_t ah[4], al[4], bh0[4], bh1[4];
            ldsm4(ah, aHi + ks * 32);
            ldsm4(al, aLo + ks * 32);
            ldsm4(bh0, bH + 256u + ks * 32);
            ldsm4(bh1, bH + (uint32_t)(16 * BSTR) + 256u + ks * 32);
            mma16816(acc[0], ah, bh0[0], bh0[1]);
            mma16816(acc[1], ah, bh0[2], bh0[3]);
            mma16816(acc[2], ah, bh1[0], bh1[1]);
            mma16816(acc[3], ah, bh1[2], bh1[3]);
            mma16816(acc[0], al, bh0[0], bh0[1]);
            mma16816(acc[1], al, bh0[2], bh0[3]);
            mma16816(acc[2], al, bh1[0], bh1[1]);
            mma16816(acc[3], al, bh1[2], bh1[3]);
        }
        __syncthreads();

        // epilogue: regs -> smem (f32) -> coalesced out / pool
        #pragma unroll
        for (int nt = 0; nt < 4; nt++) {
            int r0 = rgrp + quad;
            int c = cgrp + nt * 8 + tq * 2;
            *(float2*)&sEpi[r0 * 132 + c] = make_float2(acc[nt][0], acc[nt][1]);
            *(float2*)&sEpi[(r0 + 8) * 132 + c] = make_float2(acc[nt][2], acc[nt][3]);
        }
        __syncthreads();
        for (int idx = tid; idx < 128 * 32; idx += 1024) {
            int r = idx >> 5, q = idx & 31;
            int grow = tb + r;
            if (grow < NN) {
                float4 v = *(float4*)&sEpi[r * 132 + 4 * q];
                float4 b = *(float4*)&sBias[4 * q];
                v.x += b.x; v.y += b.y; v.z += b.z; v.w += b.w;
                if (to_pool) {
                    float* p = g_pool + (long long)g_bat[grow] * 128 + 4 * q;
                    asm volatile("red.global.add.v4.f32 [%0], {%1,%2,%3,%4};"
                                 :: "l"(p), "f"(v.x), "f"(v.y), "f"(v.z), "f"(v.w)
                                 : "memory");
                } else {
                    ((float4*)outp)[(long long)grow * 32 + q] = v;
                    ((uint2*)out16)[(long long)grow * 32 + q] =
                        make_uint2(packf16(v.x, v.y), packf16(v.z, v.w));
                }
            }
        }
        __syncthreads();
    }
}

// ---------------- head: lin1 + BN(eval) + relu + lin2 ----------------
__global__ void __launch_bounds__(128) head_kernel(
    const float* __restrict__ lin1w, const float* __restrict__ lin1b,
    const float* __restrict__ lin2w, const float* __restrict__ lin2b,
    const float* __restrict__ gamma, const float* __restrict__ beta,
    const float* __restrict__ rmean, const float* __restrict__ rvar,
    float* __restrict__ out) {
    int g = blockIdx.x;
    int c = threadIdx.x;
    __shared__ float p[128];
    __shared__ float h[128];
    p[c] = g_pool[g * 128 + c];
    __syncthreads();
    float acc = lin1b[c];
    const float* w = lin1w + c * 128;
    #pragma unroll 8
    for (int k = 0; k < 128; k++) acc += p[k] * w[k];
    acc = (acc - rmean[c]) * rsqrtf(rvar[c] + 1e-5f) * gamma[c] + beta[c];
    h[c] = fmaxf(acc, 0.f);
    __syncthreads();
    int wid = c >> 5, lane = c & 31;
    if (wid < 2) {
        const float* w2 = lin2w + wid * 128;
        float s = 0.f;
        #pragma unroll
        for (int k = lane; k < 128; k += 32) s += h[k] * w2[k];
        #pragma unroll
        for (int o = 16; o; o >>= 1) s += __shfl_xor_sync(0xffffffffu, s, o);
        if (lane == 0) out[g * 2 + wid] = s + lin2b[wid];
    }
}

// ---------------- launch ----------------
extern "C" void kernel_launch(void* const* d_in, const int* in_sizes, int n_in,
                              void* d_out, int out_size) {
    const float* x        = (const float*)d_in[0];
    const void*  ei_raw   = (const void*)d_in[1];
    const void*  bat_raw  = (const void*)d_in[2];
    const float* W1l      = (const float*)d_in[3];
    const float* b1       = (const float*)d_in[4];
    const float* W1r      = (const float*)d_in[5];
    const float* W2l      = (const float*)d_in[6];
    const float* b2       = (const float*)d_in[7];
    const float* W2r      = (const float*)d_in[8];
    const float* lin1w    = (const float*)d_in[9];
    const float* lin1b    = (const float*)d_in[10];
    const float* lin2w    = (const float*)d_in[11];
    const float* lin2b    = (const float*)d_in[12];
    const float* gamma    = (const float*)d_in[13];
    const float* beta     = (const float*)d_in[14];
    const float* rmean    = (const float*)d_in[15];
    const float* rvar     = (const float*)d_in[16];
    float* out            = (float*)d_out;

    float *agg, *h1;
    uint32_t *x16, *h116;
    cudaGetSymbolAddress((void**)&agg, g_agg);
    cudaGetSymbolAddress((void**)&h1, g_h1);
    cudaGetSymbolAddress((void**)&x16, g_x16);
    cudaGetSymbolAddress((void**)&h116, g_h116);

    cudaFuncSetAttribute(conv_mma_kernel,
                         cudaFuncAttributeMaxDynamicSharedMemorySize, SM_TOTAL);

    const int gat_grid = (NN * 32 + 255) / 256;    // warp per node

    init_kernel<<<256, 256>>>((const unsigned long long*)ei_raw,
                              (const unsigned long long*)bat_raw);
    prep_kernel<<<NB, 256>>>(ei_raw, bat_raw, x);
    gather_kernel<<<gat_grid, 256>>>(x16, agg);
    conv_mma_kernel<<<148, 1024, SM_TOTAL>>>(agg, x, W1l, b1, W1r, h1, h116, 0);
    gather_kernel<<<gat_grid, 256>>>(h116, agg);
    conv_mma_kernel<<<148, 1024, SM_TOTAL>>>(agg, h1, W2l, b2, W2r, nullptr,
                                             nullptr, 1);
    head_kernel<<<NG, 128>>>(lin1w, lin1b, lin2w, lin2b,
                             gamma, beta, rmean, rvar, out);
}

// round 15
// speedup vs baseline: 1.1099x; 1.0932x over previous
#include <cuda_runtime.h>
#include <cuda_fp16.h>
#include <cstdint>

#define NN 50000
#define NE 800000
#define NG 512
#define NB 196            // ceil(NN/256)

// ---------------- scratch ----------------
__device__ float g_agg[(size_t)NN * 128];    // holds MEAN after gather
__device__ float g_h1[(size_t)NN * 128];
__device__ uint32_t g_x16[(size_t)NN * 64];  // fp16x2 copy of x   (gather source)
__device__ uint32_t g_h116[(size_t)NN * 64]; // fp16x2 copy of h1  (gather source)
__device__ float g_pool[NG * 128];
__device__ int g_src[NE];
__device__ int g_dst[NE];
__device__ int g_ssrc[NE];                  // src ids grouped by dst (CSR)
__device__ int g_deg[NN];
__device__ int g_off[NN + 1];
__device__ int g_cur[NN];
__device__ int g_bsum[256];
__device__ int g_bat[NN];
__device__ int g_eflag = 0;   // 1 => edge_index stored as int32 (input-determined, sticky)
__device__ int g_bflag = 0;
__device__ int g_cnt0;
__device__ int g_cnt1;
__device__ int g_cnt2;

// ---------------- helpers ----------------
__device__ __forceinline__ uint32_t smem_u32(const void* p) {
    return (uint32_t)__cvta_generic_to_shared(p);
}

__device__ __forceinline__ uint32_t packf16(float a, float b) {
    __half2 h = __floats2half2_rn(a, b);
    return *(uint32_t*)&h;
}

__device__ __forceinline__ void mma16816(float* c, const uint32_t* a,
                                         uint32_t b0, uint32_t b1) {
    asm volatile(
        "mma.sync.aligned.m16n8k16.row.col.f32.f16.f16.f32 "
        "{%0,%1,%2,%3}, {%4,%5,%6,%7}, {%8,%9}, {%0,%1,%2,%3};"
        : "+f"(c[0]), "+f"(c[1]), "+f"(c[2]), "+f"(c[3])
        : "r"(a[0]), "r"(a[1]), "r"(a[2]), "r"(a[3]), "r"(b0), "r"(b1));
}

__device__ __forceinline__ void ldsm4(uint32_t* r, uint32_t addr) {
    asm volatile("ldmatrix.sync.aligned.m8n8.x4.shared.b16 {%0,%1,%2,%3}, [%4];"
                 : "=r"(r[0]), "=r"(r[1]), "=r"(r[2]), "=r"(r[3]) : "r"(addr));
}

__device__ __forceinline__ void h4acc(uint2 raw, float4& acc) {
    __half2 h0 = *(__half2*)&raw.x;
    __half2 h1 = *(__half2*)&raw.y;
    float2 f0 = __half22float2(h0);
    float2 f1 = __half22float2(h1);
    acc.x += f0.x; acc.y += f0.y; acc.z += f1.x; acc.w += f1.y;
}

// ---------------- init: zero + dtype detect ----------------
// Sample 64-bit words: true int64 indices are < 50000, so any word >= 2^32
// means the buffer actually holds packed int32 values. Flags are sticky and
// input-determined, so they are never reset (static init zeroes them once).
__global__ void init_kernel(const unsigned long long* __restrict__ e_raw,
                            const unsigned long long* __restrict__ b_raw) {
    int i = blockIdx.x * blockDim.x + threadIdx.x;
    int stride = gridDim.x * blockDim.x;
    if (i == 0) { g_cnt0 = 0; g_cnt1 = 0; g_cnt2 = 0; }
    for (int j = i; j < NN; j += stride) g_deg[j] = 0;
    for (int j = i; j < NG * 128; j += stride) g_pool[j] = 0.f;
    if (i < 4096) {
        if (e_raw[i] >= (1ull << 32)) atomicExch(&g_eflag, 1);
        if (i < 2048 && b_raw[i] >= (1ull << 32)) atomicExch(&g_bflag, 1);
    }
}

// ---------------- prep: convert + x->fp16 + scan + scatter ----------------
__device__ __forceinline__ void grid_sync(int* cnt, int t) {
    __threadfence();
    __syncthreads();
    if (t == 0) {
        atomicAdd(cnt, 1);
        while (*(volatile int*)cnt < NB) { __nanosleep(64); }
    }
    __syncthreads();
}

__global__ void __launch_bounds__(256) prep_kernel(const void* __restrict__ e_raw,
                                                   const void* __restrict__ b_raw,
                                                   const float* __restrict__ x) {
    __shared__ int s[256];
    __shared__ int bo[256];
    __shared__ int bs[256];
    int t = threadIdx.x, b = blockIdx.x;
    int i = b * 256 + t;

    // phase 0: normalize indices + degree histogram + x -> fp16
    {
        int eflag = g_eflag, bflag = g_bflag;
        for (int e = i; e < NE; e += NB * 256) {
            int ss, dd;
            if (eflag) {
                ss = ((const int*)e_raw)[e];
                dd = ((const int*)e_raw)[NE + e];
            } else {
                ss = (int)((const long long*)e_raw)[e];
                dd = (int)((const long long*)e_raw)[NE + e];
            }
            g_src[e] = ss;
            g_dst[e] = dd;
            atomicAdd(&g_deg[dd], 1);
        }
        for (int n = i; n < NN; n += NB * 256) {
            g_bat[n] = bflag ? ((const int*)b_raw)[n]
                             : (int)((const long long*)b_raw)[n];
        }
        for (int idx = i; idx < NN * 64; idx += NB * 256) {
            float2 v = ((const float2*)x)[idx];
            g_x16[idx] = packf16(v.x, v.y);
        }
    }
    grid_sync(&g_cnt0, t);

    // phase 1: block-local exclusive scan of degrees
    int d = (i < NN) ? g_deg[i] : 0;
    s[t] = d;
    __syncthreads();
    #pragma unroll
    for (int off = 1; off < 256; off <<= 1) {
        int v = (t >= off) ? s[t - off] : 0;
        __syncthreads();
        s[t] += v;
        __syncthreads();
    }
    int loc = s[t] - d;
    if (t == 255) g_bsum[b] = s[255];
    grid_sync(&g_cnt1, t);

    // phase 2: every block scans the block sums (redundant, cheap)
    int v = (t < NB) ? g_bsum[t] : 0;
    bo[t] = v; bs[t] = v;
    __syncthreads();
    #pragma unroll
    for (int off = 1; off < 256; off <<= 1) {
        int u = (t >= off) ? bs[t - off] : 0;
        __syncthreads();
        bs[t] += u;
        __syncthreads();
    }
    int base = bs[b] - bo[b];
    if (i < NN) { int o = loc + base; g_off[i] = o; g_cur[i] = o; }
    if (i == 0) g_off[NN] = NE;
    grid_sync(&g_cnt2, t);

    // phase 3: scatter src ids into CSR order
    for (int e = i; e < NE; e += NB * 256) {
        int dd = g_dst[e];
        int pos = atomicAdd(&g_cur[dd], 1);
        g_ssrc[pos] = g_src[e];
    }
}

// ---------------- CSR gather (fp16 rows): warp per dst node, writes MEAN ----
__global__ void gather_kernel(const uint32_t* __restrict__ feat16,
                              float* __restrict__ aggout) {
    int lane = threadIdx.x & 31;
    int node = (int)((blockIdx.x * (long long)blockDim.x + threadIdx.x) >> 5);
    if (node >= NN) return;
    int beg = g_off[node], end = g_off[node + 1];
    float4 acc = make_float4(0.f, 0.f, 0.f, 0.f);
    int e = beg;
    for (; e + 7 < end; e += 8) {
        uint2 v[8];
        #pragma unroll
        for (int j = 0; j < 8; j++) {
            int sj = g_ssrc[e + j];
            v[j] = ((const uint2*)feat16)[(long long)sj * 32 + lane];
        }
        #pragma unroll
        for (int j = 0; j < 8; j++) h4acc(v[j], acc);
    }
    for (; e + 3 < end; e += 4) {
        uint2 v[4];
        #pragma unroll
        for (int j = 0; j < 4; j++) {
            int sj = g_ssrc[e + j];
            v[j] = ((const uint2*)feat16)[(long long)sj * 32 + lane];
        }
        #pragma unroll
        for (int j = 0; j < 4; j++) h4acc(v[j], acc);
    }
    for (; e < end; e++) {
        int s0 = g_ssrc[e];
        h4acc(((const uint2*)feat16)[(long long)s0 * 32 + lane], acc);
    }
    float inv = 1.f / (float)max(end - beg, 1);
    acc.x *= inv; acc.y *= inv; acc.z *= inv; acc.w *= inv;
    ((float4*)(aggout + (long long)node * 128))[lane] = acc;
}

// ---------------- smem layout (bytes) ----------------
// A: [128 rows][136 f16] single precision-fp16 (34816 B).
// Epilogue f32 [128][132] (67584 B) overlaps A region. B behind both.
#define SM_BIAS 0
#define SM_AHI  512
#define SM_EPI  512
#define SM_BH   68608
#define SM_TOTAL 136192
#define ASTR 272     // A row stride bytes (136 f16)
#define BSTR 528     // B row stride bytes (264 f16)

// ---------------- SAGE conv via mma.sync fp16 (single), 1024 threads --------
// 32 warps, warp tile = 16 rows x 32 cols. A and B single fp16, fp32 accum.
// Staging loads are prefetched into registers during the previous MMA phase.
// out[i][c] = bl[c] + mean[i]@Wl[c] + xin[i]@Wr[c]   (K = 256 = [mean|x])
__global__ void __launch_bounds__(1024, 1) conv_mma_kernel(
    const float* __restrict__ meanm, const float* __restrict__ xin,
    const float* __restrict__ Wl, const float* __restrict__ bl,
    const float* __restrict__ Wr, float* __restrict__ outp,
    uint32_t* __restrict__ out16, int to_pool) {
    extern __shared__ char sm[];
    float* sBias = (float*)(sm + SM_BIAS);
    float* sEpi  = (float*)(sm + SM_EPI);
    int tid = threadIdx.x;
    int w = tid >> 5, lane = tid & 31;
    int quad = lane >> 2, tq = lane & 3;
    int rgrp = (w & 7) * 16;          // warp's 16 rows (MMA)
    int cgrp = (w >> 3) * 32;         // warp's 32 cols (MMA)

    if (tid < 128) sBias[tid] = bl[tid];

    // stage both weight matrices once: B[n][k] single fp16, k = [Wl | Wr]
    for (int idx = tid; idx < 128 * 64; idx += 1024) {
        int c = idx >> 6, p = idx & 63;
        float2 wl2 = ((const float2*)Wl)[idx];
        float2 wr2 = ((const float2*)Wr)[idx];
        *(uint32_t*)(sm + SM_BH + c * BSTR + 4 * p) = packf16(wl2.x, wl2.y);
        *(uint32_t*)(sm + SM_BH + c * BSTR + 256 + 4 * p) = packf16(wr2.x, wr2.y);
    }
    __syncthreads();

    const uint32_t smb = smem_u32(sm);
    int arow = (lane & 7) + ((lane >> 3) & 1) * 8;
    uint32_t aoff = (uint32_t)((rgrp + arow) * ASTR + (lane >> 4) * 16);
    uint32_t aHi = smb + SM_AHI + aoff;
    int brow = (lane & 7) + ((lane >> 4) & 1) * 8;
    uint32_t boff = (uint32_t)((cgrp + brow) * BSTR + ((lane >> 3) & 1) * 16);
    uint32_t bH = smb + SM_BH + boff;

    // staging item coords for this thread (4 items: idx = tid + j*1024)
    int sr[4], sq[4];
    #pragma unroll
    for (int j = 0; j < 4; j++) {
        int idx = tid + j * 1024;
        sr[j] = idx >> 5; sq[j] = idx & 31;
    }

    // prefetch first tile's mean half
    float4 pf[4];
    int tb = blockIdx.x * 128;
    #pragma unroll
    for (int j = 0; j < 4; j++) {
        int grow = tb + sr[j];
        pf[j] = (grow < NN) ? ((const float4*)meanm)[(long long)grow * 32 + sq[j]]
                            : make_float4(0.f, 0.f, 0.f, 0.f);
    }

    for (int tile = blockIdx.x; tile * 128 < NN; tile += gridDim.x) {
        tb = tile * 128;
        float acc[4][4];
        #pragma unroll
        for (int nt = 0; nt < 4; nt++)
            #pragma unroll
            for (int j = 0; j < 4; j++) acc[nt][j] = 0.f;

        // store prefetched mean half into A smem (single fp16)
        #pragma unroll
        for (int j = 0; j < 4; j++) {
            *(uint2*)(sm + SM_AHI + sr[j] * ASTR + 8 * sq[j]) =
                make_uint2(packf16(pf[j].x, pf[j].y), packf16(pf[j].z, pf[j].w));
        }
        __syncthreads();

        // prefetch root half (in flight during MMA h0)
        #pragma unroll
        for (int j = 0; j < 4; j++) {
            int grow = tb + sr[j];
            pf[j] = (grow < NN) ? ((const float4*)xin)[(long long)grow * 32 + sq[j]]
                                : make_float4(0.f, 0.f, 0.f, 0.f);
        }

        // MMA half 0 (mean @ Wl)
        #pragma unroll
        for (int ks = 0; ks < 8; ks++) {
            uint32_t ah[4], bh0[4], bh1[4];
            ldsm4(ah, aHi + ks * 32);
            ldsm4(bh0, bH + ks * 32);
            ldsm4(bh1, bH + (uint32_t)(16 * BSTR) + ks * 32);
            mma16816(acc[0], ah, bh0[0], bh0[1]);
            mma16816(acc[1], ah, bh0[2], bh0[3]);
            mma16816(acc[2], ah, bh1[0], bh1[1]);
            mma16816(acc[3], ah, bh1[2], bh1[3]);
        }
        __syncthreads();

        // store root half
        #pragma unroll
        for (int j = 0; j < 4; j++) {
            *(uint2*)(sm + SM_AHI + sr[j] * ASTR + 8 * sq[j]) =
                make_uint2(packf16(pf[j].x, pf[j].y), packf16(pf[j].z, pf[j].w));
        }
        __syncthreads();

        // prefetch next tile's mean half (in flight during MMA h1)
        {
            int ntb = tb + gridDim.x * 128;
            #pragma unroll
            for (int j = 0; j < 4; j++) {
                int grow = ntb + sr[j];
                pf[j] = (grow < NN) ? ((const float4*)meanm)[(long long)grow * 32 + sq[j]]
                                    : make_float4(0.f, 0.f, 0.f, 0.f);
            }
        }

        // MMA half 1 (x @ Wr)
        #pragma unroll
        for (int ks = 0; ks < 8; ks++) {
            uint32_t ah[4], bh0[4], bh1[4];
            ldsm4(ah, aHi + ks * 32);
            ldsm4(bh0, bH + 256u + ks * 32);
            ldsm4(bh1, bH + (uint32_t)(16 * BSTR) + 256u + ks * 32);
            mma16816(acc[0], ah, bh0[0], bh0[1]);
            mma16816(acc[1], ah, bh0[2], bh0[3]);
            mma16816(acc[2], ah, bh1[0], bh1[1]);
            mma16816(acc[3], ah, bh1[2], bh1[3]);
        }
        __syncthreads();

        // epilogue: regs -> smem (f32) -> coalesced out / pool
        #pragma unroll
        for (int nt = 0; nt < 4; nt++) {
            int r0 = rgrp + quad;
            int c = cgrp + nt * 8 + tq * 2;
            *(float2*)&sEpi[r0 * 132 + c] = make_float2(acc[nt][0], acc[nt][1]);
            *(float2*)&sEpi[(r0 + 8) * 132 + c] = make_float2(acc[nt][2], acc[nt][3]);
        }
        __syncthreads();
        for (int idx = tid; idx < 128 * 32; idx += 1024) {
            int r = idx >> 5, q = idx & 31;
            int grow = tb + r;
            if (grow < NN) {
                float4 v = *(float4*)&sEpi[r * 132 + 4 * q];
                float4 b = *(float4*)&sBias[4 * q];
                v.x += b.x; v.y += b.y; v.z += b.z; v.w += b.w;
                if (to_pool) {
                    float* p = g_pool + (long long)g_bat[grow] * 128 + 4 * q;
                    asm volatile("red.global.add.v4.f32 [%0], {%1,%2,%3,%4};"
                                 :: "l"(p), "f"(v.x), "f"(v.y), "f"(v.z), "f"(v.w)
                                 : "memory");
                } else {
                    ((float4*)outp)[(long long)grow * 32 + q] = v;
                    ((uint2*)out16)[(long long)grow * 32 + q] =
                        make_uint2(packf16(v.x, v.y), packf16(v.z, v.w));
                }
            }
        }
        __syncthreads();
    }
}

// ---------------- head: lin1 + BN(eval) + relu + lin2 ----------------
__global__ void __launch_bounds__(128) head_kernel(
    const float* __restrict__ lin1w, const float* __restrict__ lin1b,
    const float* __restrict__ lin2w, const float* __restrict__ lin2b,
    const float* __restrict__ gamma, const float* __restrict__ beta,
    const float* __restrict__ rmean, const float* __restrict__ rvar,
    float* __restrict__ out) {
    int g = blockIdx.x;
    int c = threadIdx.x;
    __shared__ float p[128];
    __shared__ float h[128];
    p[c] = g_pool[g * 128 + c];
    __syncthreads();
    float acc = lin1b[c];
    const float* w = lin1w + c * 128;
    #pragma unroll 8
    for (int k = 0; k < 128; k++) acc += p[k] * w[k];
    acc = (acc - rmean[c]) * rsqrtf(rvar[c] + 1e-5f) * gamma[c] + beta[c];
    h[c] = fmaxf(acc, 0.f);
    __syncthreads();
    int wid = c >> 5, lane = c & 31;
    if (wid < 2) {
        const float* w2 = lin2w + wid * 128;
        float s = 0.f;
        #pragma unroll
        for (int k = lane; k < 128; k += 32) s += h[k] * w2[k];
        #pragma unroll
        for (int o = 16; o; o >>= 1) s += __shfl_xor_sync(0xffffffffu, s, o);
        if (lane == 0) out[g * 2 + wid] = s + lin2b[wid];
    }
}

// ---------------- launch ----------------
extern "C" void kernel_launch(void* const* d_in, const int* in_sizes, int n_in,
                              void* d_out, int out_size) {
    const float* x        = (const float*)d_in[0];
    const void*  ei_raw   = (const void*)d_in[1];
    const void*  bat_raw  = (const void*)d_in[2];
    const float* W1l      = (const float*)d_in[3];
    const float* b1       = (const float*)d_in[4];
    const float* W1r      = (const float*)d_in[5];
    const float* W2l      = (const float*)d_in[6];
    const float* b2       = (const float*)d_in[7];
    const float* W2r      = (const float*)d_in[8];
    const float* lin1w    = (const float*)d_in[9];
    const float* lin1b    = (const float*)d_in[10];
    const float* lin2w    = (const float*)d_in[11];
    const float* lin2b    = (const float*)d_in[12];
    const float* gamma    = (const float*)d_in[13];
    const float* beta     = (const float*)d_in[14];
    const float* rmean    = (const float*)d_in[15];
    const float* rvar     = (const float*)d_in[16];
    float* out            = (float*)d_out;

    float *agg, *h1;
    uint32_t *x16, *h116;
    cudaGetSymbolAddress((void**)&agg, g_agg);
    cudaGetSymbolAddress((void**)&h1, g_h1);
    cudaGetSymbolAddress((void**)&x16, g_x16);
    cudaGetSymbolAddress((void**)&h116, g_h116);

    cudaFuncSetAttribute(conv_mma_kernel,
                         cudaFuncAttributeMaxDynamicSharedMemorySize, SM_TOTAL);

    const int gat_grid = (NN * 32 + 255) / 256;    // warp per node

    init_kernel<<<256, 256>>>((const unsigned long long*)ei_raw,
                              (const unsigned long long*)bat_raw);
    prep_kernel<<<NB, 256>>>(ei_raw, bat_raw, x);
    gather_kernel<<<gat_grid, 256>>>(x16, agg);
    conv_mma_kernel<<<148, 1024, SM_TOTAL>>>(agg, x, W1l, b1, W1r, h1, h116, 0);
    gather_kernel<<<gat_grid, 256>>>(h116, agg);
    conv_mma_kernel<<<148, 1024, SM_TOTAL>>>(agg, h1, W2l, b2, W2r, nullptr,
                                             nullptr, 1);
    head_kernel<<<NG, 128>>>(lin1w, lin1b, lin2w, lin2b,
                             gamma, beta, rmean, rvar, out);
}

// round 16
// speedup vs baseline: 1.2170x; 1.0964x over previous
#include <cuda_runtime.h>
#include <cuda_fp16.h>
#include <cstdint>

#define NN 50000
#define NE 800000
#define NG 512
#define NB 196            // ceil(NN/256)

// ---------------- scratch ----------------
__device__ uint32_t g_agg16[(size_t)NN * 64]; // MEAN as fp16x2 (gather output)
__device__ uint32_t g_x16[(size_t)NN * 64];   // fp16x2 copy of x
__device__ uint32_t g_h116[(size_t)NN * 64];  // fp16x2 h1
__device__ float g_pool[NG * 128];
__device__ int g_src[NE];
__device__ int g_dst[NE];
__device__ int g_ssrc[NE];                  // src ids grouped by dst (CSR)
__device__ int g_deg[NN];
__device__ int g_off[NN + 1];
__device__ int g_cur[NN];
__device__ int g_bsum[256];
__device__ int g_bat[NN];
__device__ int g_eflag = 0;   // 1 => edge_index stored as int32 (input-determined, sticky)
__device__ int g_bflag = 0;
__device__ int g_cnt0;
__device__ int g_cnt1;
__device__ int g_cnt2;

// ---------------- helpers ----------------
__device__ __forceinline__ uint32_t smem_u32(const void* p) {
    return (uint32_t)__cvta_generic_to_shared(p);
}

__device__ __forceinline__ uint32_t packf16(float a, float b) {
    __half2 h = __floats2half2_rn(a, b);
    return *(uint32_t*)&h;
}

__device__ __forceinline__ void mma16816(float* c, const uint32_t* a,
                                         uint32_t b0, uint32_t b1) {
    asm volatile(
        "mma.sync.aligned.m16n8k16.row.col.f32.f16.f16.f32 "
        "{%0,%1,%2,%3}, {%4,%5,%6,%7}, {%8,%9}, {%0,%1,%2,%3};"
        : "+f"(c[0]), "+f"(c[1]), "+f"(c[2]), "+f"(c[3])
        : "r"(a[0]), "r"(a[1]), "r"(a[2]), "r"(a[3]), "r"(b0), "r"(b1));
}

__device__ __forceinline__ void ldsm4(uint32_t* r, uint32_t addr) {
    asm volatile("ldmatrix.sync.aligned.m8n8.x4.shared.b16 {%0,%1,%2,%3}, [%4];"
                 : "=r"(r[0]), "=r"(r[1]), "=r"(r[2]), "=r"(r[3]) : "r"(addr));
}

__device__ __forceinline__ void h4acc(uint2 raw, float4& acc) {
    __half2 h0 = *(__half2*)&raw.x;
    __half2 h1 = *(__half2*)&raw.y;
    float2 f0 = __half22float2(h0);
    float2 f1 = __half22float2(h1);
    acc.x += f0.x; acc.y += f0.y; acc.z += f1.x; acc.w += f1.y;
}

// ---------------- init: zero + dtype detect ----------------
// Sample 64-bit words: true int64 indices are < 50000, so any word >= 2^32
// means the buffer actually holds packed int32 values. Flags are sticky and
// input-determined, so they are never reset (static init zeroes them once).
__global__ void init_kernel(const unsigned long long* __restrict__ e_raw,
                            const unsigned long long* __restrict__ b_raw) {
    int i = blockIdx.x * blockDim.x + threadIdx.x;
    int stride = gridDim.x * blockDim.x;
    if (i == 0) { g_cnt0 = 0; g_cnt1 = 0; g_cnt2 = 0; }
    for (int j = i; j < NN; j += stride) g_deg[j] = 0;
    for (int j = i; j < NG * 128; j += stride) g_pool[j] = 0.f;
    if (i < 4096) {
        if (e_raw[i] >= (1ull << 32)) atomicExch(&g_eflag, 1);
        if (i < 2048 && b_raw[i] >= (1ull << 32)) atomicExch(&g_bflag, 1);
    }
}

// ---------------- prep: convert + x->fp16 + scan + scatter ----------------
__device__ __forceinline__ void grid_sync(int* cnt, int t) {
    __threadfence();
    __syncthreads();
    if (t == 0) {
        atomicAdd(cnt, 1);
        while (*(volatile int*)cnt < NB) { __nanosleep(64); }
    }
    __syncthreads();
}

__global__ void __launch_bounds__(256) prep_kernel(const void* __restrict__ e_raw,
                                                   const void* __restrict__ b_raw,
                                                   const float* __restrict__ x) {
    __shared__ int s[256];
    __shared__ int bo[256];
    __shared__ int bs[256];
    int t = threadIdx.x, b = blockIdx.x;
    int i = b * 256 + t;

    // phase 0: normalize indices + degree histogram + x -> fp16
    {
        int eflag = g_eflag, bflag = g_bflag;
        for (int e = i; e < NE; e += NB * 256) {
            int ss, dd;
            if (eflag) {
                ss = ((const int*)e_raw)[e];
                dd = ((const int*)e_raw)[NE + e];
            } else {
                ss = (int)((const long long*)e_raw)[e];
                dd = (int)((const long long*)e_raw)[NE + e];
            }
            g_src[e] = ss;
            g_dst[e] = dd;
            atomicAdd(&g_deg[dd], 1);
        }
        for (int n = i; n < NN; n += NB * 256) {
            g_bat[n] = bflag ? ((const int*)b_raw)[n]
                             : (int)((const long long*)b_raw)[n];
        }
        for (int idx = i; idx < NN * 64; idx += NB * 256) {
            float2 v = ((const float2*)x)[idx];
            g_x16[idx] = packf16(v.x, v.y);
        }
    }
    grid_sync(&g_cnt0, t);

    // phase 1: block-local exclusive scan of degrees
    int d = (i < NN) ? g_deg[i] : 0;
    s[t] = d;
    __syncthreads();
    #pragma unroll
    for (int off = 1; off < 256; off <<= 1) {
        int v = (t >= off) ? s[t - off] : 0;
        __syncthreads();
        s[t] += v;
        __syncthreads();
    }
    int loc = s[t] - d;
    if (t == 255) g_bsum[b] = s[255];
    grid_sync(&g_cnt1, t);

    // phase 2: every block scans the block sums (redundant, cheap)
    int v = (t < NB) ? g_bsum[t] : 0;
    bo[t] = v; bs[t] = v;
    __syncthreads();
    #pragma unroll
    for (int off = 1; off < 256; off <<= 1) {
        int u = (t >= off) ? bs[t - off] : 0;
        __syncthreads();
        bs[t] += u;
        __syncthreads();
    }
    int base = bs[b] - bo[b];
    if (i < NN) { int o = loc + base; g_off[i] = o; g_cur[i] = o; }
    if (i == 0) g_off[NN] = NE;
    grid_sync(&g_cnt2, t);

    // phase 3: scatter src ids into CSR order
    for (int e = i; e < NE; e += NB * 256) {
        int dd = g_dst[e];
        int pos = atomicAdd(&g_cur[dd], 1);
        g_ssrc[pos] = g_src[e];
    }
}

// ---------------- CSR gather (fp16 rows): warp per dst node ----------------
// Accumulates fp32, writes MEAN as fp16x2 (the conv rounds to fp16 anyway).
__global__ void gather_kernel(const uint32_t* __restrict__ feat16,
                              uint32_t* __restrict__ agg16) {
    int lane = threadIdx.x & 31;
    int node = (int)((blockIdx.x * (long long)blockDim.x + threadIdx.x) >> 5);
    if (node >= NN) return;
    int beg = g_off[node], end = g_off[node + 1];
    float4 acc = make_float4(0.f, 0.f, 0.f, 0.f);
    int e = beg;
    for (; e + 7 < end; e += 8) {
        uint2 v[8];
        #pragma unroll
        for (int j = 0; j < 8; j++) {
            int sj = g_ssrc[e + j];
            v[j] = ((const uint2*)feat16)[(long long)sj * 32 + lane];
        }
        #pragma unroll
        for (int j = 0; j < 8; j++) h4acc(v[j], acc);
    }
    for (; e + 3 < end; e += 4) {
        uint2 v[4];
        #pragma unroll
        for (int j = 0; j < 4; j++) {
            int sj = g_ssrc[e + j];
            v[j] = ((const uint2*)feat16)[(long long)sj * 32 + lane];
        }
        #pragma unroll
        for (int j = 0; j < 4; j++) h4acc(v[j], acc);
    }
    for (; e < end; e++) {
        int s0 = g_ssrc[e];
        h4acc(((const uint2*)feat16)[(long long)s0 * 32 + lane], acc);
    }
    float inv = 1.f / (float)max(end - beg, 1);
    ((uint2*)agg16)[(long long)node * 32 + lane] =
        make_uint2(packf16(acc.x * inv, acc.y * inv),
                   packf16(acc.z * inv, acc.w * inv));
}

// ---------------- smem layout (bytes) ----------------
// A: [128 rows][136 f16] (34816 B). Epilogue f32 [128][132] overlaps A. B behind.
#define SM_BIAS 0
#define SM_AHI  512
#define SM_EPI  512
#define SM_BH   68608
#define SM_TOTAL 136192
#define ASTR 272     // A row stride bytes (136 f16)
#define BSTR 528     // B row stride bytes (264 f16)

// ---------------- SAGE conv via mma.sync fp16, 1024 threads -----------------
// 32 warps, warp tile = 16 rows x 32 cols. All operands fp16, fp32 accum.
// Staging = pure uint2 copies (sources already fp16); prefetched during MMA.
// out[i][c] = bl[c] + mean[i]@Wl[c] + xin[i]@Wr[c]   (K = 256 = [mean|x])
__global__ void __launch_bounds__(1024, 1) conv_mma_kernel(
    const uint32_t* __restrict__ mean16, const uint32_t* __restrict__ xin16,
    const float* __restrict__ Wl, const float* __restrict__ bl,
    const float* __restrict__ Wr, uint32_t* __restrict__ out16, int to_pool) {
    extern __shared__ char sm[];
    float* sBias = (float*)(sm + SM_BIAS);
    float* sEpi  = (float*)(sm + SM_EPI);
    int tid = threadIdx.x;
    int w = tid >> 5, lane = tid & 31;
    int quad = lane >> 2, tq = lane & 3;
    int rgrp = (w & 7) * 16;          // warp's 16 rows (MMA)
    int cgrp = (w >> 3) * 32;         // warp's 32 cols (MMA)

    if (tid < 128) sBias[tid] = bl[tid];

    // stage both weight matrices once: B[n][k] single fp16, k = [Wl | Wr]
    for (int idx = tid; idx < 128 * 64; idx += 1024) {
        int c = idx >> 6, p = idx & 63;
        float2 wl2 = ((const float2*)Wl)[idx];
        float2 wr2 = ((const float2*)Wr)[idx];
        *(uint32_t*)(sm + SM_BH + c * BSTR + 4 * p) = packf16(wl2.x, wl2.y);
        *(uint32_t*)(sm + SM_BH + c * BSTR + 256 + 4 * p) = packf16(wr2.x, wr2.y);
    }
    __syncthreads();

    const uint32_t smb = smem_u32(sm);
    int arow = (lane & 7) + ((lane >> 3) & 1) * 8;
    uint32_t aoff = (uint32_t)((rgrp + arow) * ASTR + (lane >> 4) * 16);
    uint32_t aHi = smb + SM_AHI + aoff;
    int brow = (lane & 7) + ((lane >> 4) & 1) * 8;
    uint32_t boff = (uint32_t)((cgrp + brow) * BSTR + ((lane >> 3) & 1) * 16);
    uint32_t bH = smb + SM_BH + boff;

    // staging item coords for this thread (4 items: idx = tid + j*1024)
    int sr[4], sq[4];
    #pragma unroll
    for (int j = 0; j < 4; j++) {
        int idx = tid + j * 1024;
        sr[j] = idx >> 5; sq[j] = idx & 31;
    }

    // prefetch first tile's mean half (fp16 uint2 rows)
    uint2 pf[4];
    int tb = blockIdx.x * 128;
    #pragma unroll
    for (int j = 0; j < 4; j++) {
        int grow = tb + sr[j];
        pf[j] = (grow < NN) ? ((const uint2*)mean16)[(long long)grow * 32 + sq[j]]
                            : make_uint2(0u, 0u);
    }

    for (int tile = blockIdx.x; tile * 128 < NN; tile += gridDim.x) {
        tb = tile * 128;
        float acc[4][4];
        #pragma unroll
        for (int nt = 0; nt < 4; nt++)
            #pragma unroll
            for (int j = 0; j < 4; j++) acc[nt][j] = 0.f;

        // store prefetched mean half into A smem (pure copy)
        #pragma unroll
        for (int j = 0; j < 4; j++)
            *(uint2*)(sm + SM_AHI + sr[j] * ASTR + 8 * sq[j]) = pf[j];
        __syncthreads();

        // prefetch root half (in flight during MMA h0)
        #pragma unroll
        for (int j = 0; j < 4; j++) {
            int grow = tb + sr[j];
            pf[j] = (grow < NN) ? ((const uint2*)xin16)[(long long)grow * 32 + sq[j]]
                                : make_uint2(0u, 0u);
        }

        // MMA half 0 (mean @ Wl)
        #pragma unroll
        for (int ks = 0; ks < 8; ks++) {
            uint32_t ah[4], bh0[4], bh1[4];
            ldsm4(ah, aHi + ks * 32);
            ldsm4(bh0, bH + ks * 32);
            ldsm4(bh1, bH + (uint32_t)(16 * BSTR) + ks * 32);
            mma16816(acc[0], ah, bh0[0], bh0[1]);
            mma16816(acc[1], ah, bh0[2], bh0[3]);
            mma16816(acc[2], ah, bh1[0], bh1[1]);
            mma16816(acc[3], ah, bh1[2], bh1[3]);
        }
        __syncthreads();

        // store root half (pure copy)
        #pragma unroll
        for (int j = 0; j < 4; j++)
            *(uint2*)(sm + SM_AHI + sr[j] * ASTR + 8 * sq[j]) = pf[j];
        __syncthreads();

        // prefetch next tile's mean half (in flight during MMA h1)
        {
            int ntb = tb + gridDim.x * 128;
            #pragma unroll
            for (int j = 0; j < 4; j++) {
                int grow = ntb + sr[j];
                pf[j] = (grow < NN)
                      ? ((const uint2*)mean16)[(long long)grow * 32 + sq[j]]
                      : make_uint2(0u, 0u);
            }
        }

        // MMA half 1 (x @ Wr)
        #pragma unroll
        for (int ks = 0; ks < 8; ks++) {
            uint32_t ah[4], bh0[4], bh1[4];
            ldsm4(ah, aHi + ks * 32);
            ldsm4(bh0, bH + 256u + ks * 32);
            ldsm4(bh1, bH + (uint32_t)(16 * BSTR) + 256u + ks * 32);
            mma16816(acc[0], ah, bh0[0], bh0[1]);
            mma16816(acc[1], ah, bh0[2], bh0[3]);
            mma16816(acc[2], ah, bh1[0], bh1[1]);
            mma16816(acc[3], ah, bh1[2], bh1[3]);
        }
        __syncthreads();

        // epilogue: regs -> smem (f32) -> coalesced out / pool
        #pragma unroll
        for (int nt = 0; nt < 4; nt++) {
            int r0 = rgrp + quad;
            int c = cgrp + nt * 8 + tq * 2;
            *(float2*)&sEpi[r0 * 132 + c] = make_float2(acc[nt][0], acc[nt][1]);
            *(float2*)&sEpi[(r0 + 8) * 132 + c] = make_float2(acc[nt][2], acc[nt][3]);
        }
        __syncthreads();
        for (int idx = tid; idx < 128 * 32; idx += 1024) {
            int r = idx >> 5, q = idx & 31;
            int grow = tb + r;
            if (grow < NN) {
                float4 v = *(float4*)&sEpi[r * 132 + 4 * q];
                float4 b = *(float4*)&sBias[4 * q];
                v.x += b.x; v.y += b.y; v.z += b.z; v.w += b.w;
                if (to_pool) {
                    float* p = g_pool + (long long)g_bat[grow] * 128 + 4 * q;
                    asm volatile("red.global.add.v4.f32 [%0], {%1,%2,%3,%4};"
                                 :: "l"(p), "f"(v.x), "f"(v.y), "f"(v.z), "f"(v.w)
                                 : "memory");
                } else {
                    ((uint2*)out16)[(long long)grow * 32 + q] =
                        make_uint2(packf16(v.x, v.y), packf16(v.z, v.w));
                }
            }
        }
        __syncthreads();
    }
}

// ---------------- head: lin1 + BN(eval) + relu + lin2 ----------------
__global__ void __launch_bounds__(128) head_kernel(
    const float* __restrict__ lin1w, const float* __restrict__ lin1b,
    const float* __restrict__ lin2w, const float* __restrict__ lin2b,
    const float* __restrict__ gamma, const float* __restrict__ beta,
    const float* __restrict__ rmean, const float* __restrict__ rvar,
    float* __restrict__ out) {
    int g = blockIdx.x;
    int c = threadIdx.x;
    __shared__ float p[128];
    __shared__ float h[128];
    p[c] = g_pool[g * 128 + c];
    __syncthreads();
    float acc = lin1b[c];
    const float* w = lin1w + c * 128;
    #pragma unroll 8
    for (int k = 0; k < 128; k++) acc += p[k] * w[k];
    acc = (acc - rmean[c]) * rsqrtf(rvar[c] + 1e-5f) * gamma[c] + beta[c];
    h[c] = fmaxf(acc, 0.f);
    __syncthreads();
    int wid = c >> 5, lane = c & 31;
    if (wid < 2) {
        const float* w2 = lin2w + wid * 128;
        float s = 0.f;
        #pragma unroll
        for (int k = lane; k < 128; k += 32) s += h[k] * w2[k];
        #pragma unroll
        for (int o = 16; o; o >>= 1) s += __shfl_xor_sync(0xffffffffu, s, o);
        if (lane == 0) out[g * 2 + wid] = s + lin2b[wid];
    }
}

// ---------------- launch ----------------
extern "C" void kernel_launch(void* const* d_in, const int* in_sizes, int n_in,
                              void* d_out, int out_size) {
    const float* x        = (const float*)d_in[0];
    const void*  ei_raw   = (const void*)d_in[1];
    const void*  bat_raw  = (const void*)d_in[2];
    const float* W1l      = (const float*)d_in[3];
    const float* b1       = (const float*)d_in[4];
    const float* W1r      = (const float*)d_in[5];
    const float* W2l      = (const float*)d_in[6];
    const float* b2       = (const float*)d_in[7];
    const float* W2r      = (const float*)d_in[8];
    const float* lin1w    = (const float*)d_in[9];
    const float* lin1b    = (const float*)d_in[10];
    const float* lin2w    = (const float*)d_in[11];
    const float* lin2b    = (const float*)d_in[12];
    const float* gamma    = (const float*)d_in[13];
    const float* beta     = (const float*)d_in[14];
    const float* rmean    = (const float*)d_in[15];
    const float* rvar     = (const float*)d_in[16];
    float* out            = (float*)d_out;

    uint32_t *agg16, *x16, *h116;
    cudaGetSymbolAddress((void**)&agg16, g_agg16);
    cudaGetSymbolAddress((void**)&x16, g_x16);
    cudaGetSymbolAddress((void**)&h116, g_h116);

    cudaFuncSetAttribute(conv_mma_kernel,
                         cudaFuncAttributeMaxDynamicSharedMemorySize, SM_TOTAL);

    const int gat_grid = (NN * 32 + 255) / 256;    // warp per node

    init_kernel<<<256, 256>>>((const unsigned long long*)ei_raw,
                              (const unsigned long long*)bat_raw);
    prep_kernel<<<NB, 256>>>(ei_raw, bat_raw, x);
    gather_kernel<<<gat_grid, 256>>>(x16, agg16);
    conv_mma_kernel<<<148, 1024, SM_TOTAL>>>(agg16, x16, W1l, b1, W1r, h116, 0);
    gather_kernel<<<gat_grid, 256>>>(h116, agg16);
    conv_mma_kernel<<<148, 1024, SM_TOTAL>>>(agg16, h116, W2l, b2, W2r,
                                             nullptr, 1);
    head_kernel<<<NG, 128>>>(lin1w, lin1b, lin2w, lin2b,
                             gamma, beta, rmean, rvar, out);
}